// round 3
// baseline (speedup 1.0000x reference)
#include <cuda_runtime.h>
#include <cstdint>

#define BB 64
#define NN 1024
#define MM 1024
#define DD 512

typedef unsigned long long u64;

// ---------------- scratch (device globals: allocation-free) ----------------
__device__ float g_S [(size_t)BB * NN * MM];   // similarity logits   [B][N][M]
__device__ float g_Ar[(size_t)BB * NN * MM];   // row-softmax weights [B][N][M]
__device__ float g_Ac[(size_t)BB * MM * NN];   // col-softmax weights, transposed [B][M][N]
__device__ float g_rmax[BB * NN];
__device__ float g_rinv[BB * NN];
__device__ float g_cmax[BB * MM];
__device__ float g_cinv[BB * MM];

// ---------------- packed fp32 helpers ----------------
__device__ __forceinline__ u64 dup2(float x) {
    unsigned int u = __float_as_uint(x);
    u64 r;
    asm("mov.b64 %0, {%1, %1};" : "=l"(r) : "r"(u));
    return r;
}
__device__ __forceinline__ void ffma2(u64& acc, u64 a, u64 b) {
    asm("fma.rn.f32x2 %0, %1, %2, %0;" : "+l"(acc) : "l"(a), "l"(b));
}

union F4U2 { float4 f; u64 u[2]; };

// ---------------------------------------------------------------------------
// Packed SGEMM NT:  C[b] = A[b] (Mr x K, k-contig) * B[b]^T (Nc x K, k-contig)
// 128x128x8 tile, 256 threads, 8x8 microtile computed as 8x4 f32x2 pairs.
// A smem tile stored duplicated ({a,a} u64) so packed FMA needs no repacking.
// ---------------------------------------------------------------------------
__global__ __launch_bounds__(256, 2) void sgemm_nt_kernel(
    const float* __restrict__ A, const float* __restrict__ Bm,
    float* __restrict__ C, int Mr, int Nc, int K)
{
    __shared__ u64   As2[8][128];   // duplicated A values
    __shared__ float Bs [8][128];

    const int bz = blockIdx.z;
    const float* Ab = A  + (size_t)bz * Mr * K;
    const float* Bb = Bm + (size_t)bz * Nc * K;
    float*       Cb = C  + (size_t)bz * Mr * Nc;

    const int m0 = blockIdx.y * 128;
    const int n0 = blockIdx.x * 128;
    const int t  = threadIdx.x;
    const int lrow = t >> 1;           // 0..127
    const int lk   = (t & 1) * 4;      // 0 or 4
    const int tx = t & 15, ty = t >> 4;

    u64 acc[8][4];
#pragma unroll
    for (int i = 0; i < 8; i++)
#pragma unroll
        for (int j = 0; j < 4; j++) acc[i][j] = 0ull;

    for (int kt = 0; kt < K; kt += 8) {
        float4 av = *(const float4*)(Ab + (size_t)(m0 + lrow) * K + kt + lk);
        float4 bv = *(const float4*)(Bb + (size_t)(n0 + lrow) * K + kt + lk);
        As2[lk + 0][lrow] = dup2(av.x); As2[lk + 1][lrow] = dup2(av.y);
        As2[lk + 2][lrow] = dup2(av.z); As2[lk + 3][lrow] = dup2(av.w);
        Bs[lk + 0][lrow] = bv.x; Bs[lk + 1][lrow] = bv.y;
        Bs[lk + 2][lrow] = bv.z; Bs[lk + 3][lrow] = bv.w;
        __syncthreads();
#pragma unroll
        for (int k = 0; k < 8; k++) {
            ulonglong2 A01 = *(const ulonglong2*)&As2[k][ty * 8 + 0];
            ulonglong2 A23 = *(const ulonglong2*)&As2[k][ty * 8 + 2];
            ulonglong2 A45 = *(const ulonglong2*)&As2[k][ty * 8 + 4];
            ulonglong2 A67 = *(const ulonglong2*)&As2[k][ty * 8 + 6];
            F4U2 b0, b1;
            b0.f = *(const float4*)&Bs[k][tx * 8];
            b1.f = *(const float4*)&Bs[k][tx * 8 + 4];
            u64 a[8] = {A01.x, A01.y, A23.x, A23.y, A45.x, A45.y, A67.x, A67.y};
            u64 b[4] = {b0.u[0], b0.u[1], b1.u[0], b1.u[1]};
#pragma unroll
            for (int i = 0; i < 8; i++)
#pragma unroll
                for (int j = 0; j < 4; j++) ffma2(acc[i][j], a[i], b[j]);
        }
        __syncthreads();
    }

#pragma unroll
    for (int i = 0; i < 8; i++) {
        size_t row = (size_t)(m0 + ty * 8 + i) * Nc + n0 + tx * 8;
        ulonglong2 v0; v0.x = acc[i][0]; v0.y = acc[i][1];
        ulonglong2 v1; v1.x = acc[i][2]; v1.y = acc[i][3];
        *(ulonglong2*)(Cb + row)     = v0;
        *(ulonglong2*)(Cb + row + 4) = v1;
    }
}

// ---------------------------------------------------------------------------
// Packed SGEMM NN:  C[b] = A[b] (Mr x K, k-contig) * B[b] (K x Nc, n-contig)
// ---------------------------------------------------------------------------
__global__ __launch_bounds__(256, 2) void sgemm_nn_kernel(
    const float* __restrict__ A, const float* __restrict__ Bm,
    float* __restrict__ C, int Mr, int Nc, int K)
{
    __shared__ u64   As2[8][128];
    __shared__ float Bs [8][128];

    const int bz = blockIdx.z;
    const float* Ab = A  + (size_t)bz * Mr * K;
    const float* Bb = Bm + (size_t)bz * K * Nc;
    float*       Cb = C  + (size_t)bz * Mr * Nc;

    const int m0 = blockIdx.y * 128;
    const int n0 = blockIdx.x * 128;
    const int t  = threadIdx.x;
    const int lrow  = t >> 1;            // A: 0..127
    const int lk    = (t & 1) * 4;
    const int lrowB = t >> 5;            // B: 0..7 (k)
    const int lcolB = (t & 31) * 4;      // B: 0..124
    const int tx = t & 15, ty = t >> 4;

    u64 acc[8][4];
#pragma unroll
    for (int i = 0; i < 8; i++)
#pragma unroll
        for (int j = 0; j < 4; j++) acc[i][j] = 0ull;

    for (int kt = 0; kt < K; kt += 8) {
        float4 av = *(const float4*)(Ab + (size_t)(m0 + lrow) * K + kt + lk);
        float4 bv = *(const float4*)(Bb + (size_t)(kt + lrowB) * Nc + n0 + lcolB);
        As2[lk + 0][lrow] = dup2(av.x); As2[lk + 1][lrow] = dup2(av.y);
        As2[lk + 2][lrow] = dup2(av.z); As2[lk + 3][lrow] = dup2(av.w);
        *(float4*)&Bs[lrowB][lcolB] = bv;
        __syncthreads();
#pragma unroll
        for (int k = 0; k < 8; k++) {
            ulonglong2 A01 = *(const ulonglong2*)&As2[k][ty * 8 + 0];
            ulonglong2 A23 = *(const ulonglong2*)&As2[k][ty * 8 + 2];
            ulonglong2 A45 = *(const ulonglong2*)&As2[k][ty * 8 + 4];
            ulonglong2 A67 = *(const ulonglong2*)&As2[k][ty * 8 + 6];
            F4U2 b0, b1;
            b0.f = *(const float4*)&Bs[k][tx * 8];
            b1.f = *(const float4*)&Bs[k][tx * 8 + 4];
            u64 a[8] = {A01.x, A01.y, A23.x, A23.y, A45.x, A45.y, A67.x, A67.y};
            u64 b[4] = {b0.u[0], b0.u[1], b1.u[0], b1.u[1]};
#pragma unroll
            for (int i = 0; i < 8; i++)
#pragma unroll
                for (int j = 0; j < 4; j++) ffma2(acc[i][j], a[i], b[j]);
        }
        __syncthreads();
    }

#pragma unroll
    for (int i = 0; i < 8; i++) {
        size_t row = (size_t)(m0 + ty * 8 + i) * Nc + n0 + tx * 8;
        ulonglong2 v0; v0.x = acc[i][0]; v0.y = acc[i][1];
        ulonglong2 v1; v1.x = acc[i][2]; v1.y = acc[i][3];
        *(ulonglong2*)(Cb + row)     = v0;
        *(ulonglong2*)(Cb + row + 4) = v1;
    }
}

// ---------------------------------------------------------------------------
// Row stats: per (b,n), max and 1/sum(exp) over m (1024 elems).
// ---------------------------------------------------------------------------
__global__ __launch_bounds__(256) void row_stats_kernel(
    const float* __restrict__ S, float* __restrict__ rmax, float* __restrict__ rinv)
{
    const int n = blockIdx.x, b = blockIdx.y;
    const float* row = S + ((size_t)b * NN + n) * MM;
    const int t = threadIdx.x;
    float4 v = *(const float4*)(row + t * 4);

    float mx = fmaxf(fmaxf(v.x, v.y), fmaxf(v.z, v.w));
#pragma unroll
    for (int o = 16; o; o >>= 1) mx = fmaxf(mx, __shfl_xor_sync(0xffffffffu, mx, o));

    __shared__ float smx[8];
    const int w = t >> 5, lane = t & 31;
    if (lane == 0) smx[w] = mx;
    __syncthreads();
    float gmx = smx[0];
#pragma unroll
    for (int i = 1; i < 8; i++) gmx = fmaxf(gmx, smx[i]);

    float s = __expf(v.x - gmx) + __expf(v.y - gmx) + __expf(v.z - gmx) + __expf(v.w - gmx);
#pragma unroll
    for (int o = 16; o; o >>= 1) s += __shfl_xor_sync(0xffffffffu, s, o);

    __shared__ float ssm[8];
    if (lane == 0) ssm[w] = s;
    __syncthreads();
    if (t == 0) {
        float tot = ssm[0];
#pragma unroll
        for (int i = 1; i < 8; i++) tot += ssm[i];
        rmax[b * NN + n] = gmx;
        rinv[b * NN + n] = 1.0f / tot;
    }
}

// ---------------------------------------------------------------------------
// Col stats: online softmax over n for 32 columns per block (coalesced).
// ---------------------------------------------------------------------------
__global__ __launch_bounds__(256) void col_stats_kernel(
    const float* __restrict__ S, float* __restrict__ cmax, float* __restrict__ cinv)
{
    const int b = blockIdx.y;
    const int c0 = blockIdx.x * 32;
    const int t = threadIdx.x, w = t >> 5, lane = t & 31;
    const float* Sb = S + (size_t)b * NN * MM;

    float m_run = -3.0e38f, s_run = 0.0f;
    for (int n = w; n < NN; n += 8) {
        float v = Sb[(size_t)n * MM + c0 + lane];
        if (v <= m_run) {
            s_run += __expf(v - m_run);
        } else {
            s_run = s_run * __expf(m_run - v) + 1.0f;
            m_run = v;
        }
    }

    __shared__ float smx[8][32];
    __shared__ float ssm[8][32];
    smx[w][lane] = m_run;
    ssm[w][lane] = s_run;
    __syncthreads();
    if (w == 0) {
        float m = smx[0][lane], s = ssm[0][lane];
#pragma unroll
        for (int i = 1; i < 8; i++) {
            float m2 = smx[i][lane], s2 = ssm[i][lane];
            float nm = fmaxf(m, m2);
            s = s * __expf(m - nm) + s2 * __expf(m2 - nm);
            m = nm;
        }
        cmax[b * MM + c0 + lane] = m;
        cinv[b * MM + c0 + lane] = 1.0f / s;
    }
}

// ---------------------------------------------------------------------------
// Materialize both normalized weight matrices in one pass over S.
// ---------------------------------------------------------------------------
__global__ __launch_bounds__(256) void softmax_weights_kernel(
    const float* __restrict__ S,
    const float* __restrict__ rmax, const float* __restrict__ rinv,
    const float* __restrict__ cmax, const float* __restrict__ cinv,
    float* __restrict__ Ar, float* __restrict__ AcT)
{
    __shared__ float tile[32][33];
    const int b = blockIdx.z;
    const int n0 = blockIdx.y * 32, m0 = blockIdx.x * 32;
    const int tx = threadIdx.x, ty = threadIdx.y;

    const float cm = cmax[b * MM + m0 + tx];
    const float ci = cinv[b * MM + m0 + tx];

#pragma unroll
    for (int r = ty; r < 32; r += 8) {
        const int n = n0 + r;
        const float s  = S[((size_t)b * NN + n) * MM + m0 + tx];
        const float rm = rmax[b * NN + n];
        const float ri = rinv[b * NN + n];
        Ar[((size_t)b * NN + n) * MM + m0 + tx] = __expf(s - rm) * ri;
        tile[r][tx] = __expf(s - cm) * ci;
    }
    __syncthreads();
#pragma unroll
    for (int r = ty; r < 32; r += 8) {
        const int m = m0 + r;
        AcT[((size_t)b * MM + m) * NN + n0 + tx] = tile[tx][r];
    }
}

// ---------------------------------------------------------------------------
extern "C" void kernel_launch(void* const* d_in, const int* in_sizes, int n_in,
                              void* d_out, int out_size)
{
    (void)in_sizes; (void)n_in; (void)out_size;
    const float* P = (const float*)d_in[0];   // premise    [B][N][D]
    const float* H = (const float*)d_in[1];   // hypothesis [B][M][D]

    float* out1 = (float*)d_out;                              // premise_aligned    [B][N][D]
    float* out2 = (float*)d_out + (size_t)BB * NN * DD;       // hypothesis_aligned [B][M][D]

    float *pS, *pAr, *pAc, *prmax, *prinv, *pcmax, *pcinv;
    cudaGetSymbolAddress((void**)&pS,    g_S);
    cudaGetSymbolAddress((void**)&pAr,   g_Ar);
    cudaGetSymbolAddress((void**)&pAc,   g_Ac);
    cudaGetSymbolAddress((void**)&prmax, g_rmax);
    cudaGetSymbolAddress((void**)&prinv, g_rinv);
    cudaGetSymbolAddress((void**)&pcmax, g_cmax);
    cudaGetSymbolAddress((void**)&pcinv, g_cinv);

    // 1) S = P * H^T
    sgemm_nt_kernel<<<dim3(MM / 128, NN / 128, BB), 256>>>(P, H, pS, NN, MM, DD);

    // 2) softmax stats
    row_stats_kernel<<<dim3(NN, BB), 256>>>(pS, prmax, prinv);
    col_stats_kernel<<<dim3(MM / 32, BB), 256>>>(pS, pcmax, pcinv);

    // 3) normalized weights
    softmax_weights_kernel<<<dim3(MM / 32, NN / 32, BB), dim3(32, 8)>>>(
        pS, prmax, prinv, pcmax, pcinv, pAr, pAc);

    // 4) premise_aligned = A_row * H
    sgemm_nn_kernel<<<dim3(DD / 128, NN / 128, BB), 256>>>(pAr, H, out1, NN, DD, MM);

    // 5) hypothesis_aligned = A_colT * P
    sgemm_nn_kernel<<<dim3(DD / 128, MM / 128, BB), 256>>>(pAc, P, out2, MM, DD, NN);
}

// round 4
// speedup vs baseline: 1.6575x; 1.6575x over previous
#include <cuda_runtime.h>
#include <cstdint>

#define BB 64
#define NN 1024
#define MM 1024
#define DD 512

typedef unsigned long long u64;
typedef unsigned int u32;

// ---------------- scratch (device globals: allocation-free) ----------------
__device__ float g_S [(size_t)BB * NN * MM];   // similarity logits   [B][N][M]
__device__ float g_Ar[(size_t)BB * NN * MM];   // row-softmax weights [B][N][M]
__device__ float g_Ac[(size_t)BB * MM * NN];   // col-softmax weights, transposed [B][M][N]
__device__ float g_rmax[BB * NN];
__device__ float g_rinv[BB * NN];
__device__ float g_cmax[BB * MM];
__device__ float g_cinv[BB * MM];

// ---------------- helpers ----------------
__device__ __forceinline__ float tf32r(float x) {
    float r; asm("cvt.rna.tf32.f32 %0, %1;" : "=f"(r) : "f"(x)); return r;
}
__device__ __forceinline__ u64 pk(float lo, float hi) {
    u64 r;
    asm("mov.b64 %0, {%1, %2};" : "=l"(r) : "r"(__float_as_uint(lo)), "r"(__float_as_uint(hi)));
    return r;
}
__device__ __forceinline__ u32 lo32(u64 v) { return (u32)v; }
__device__ __forceinline__ u32 hi32(u64 v) { return (u32)(v >> 32); }

__device__ __forceinline__ void mma8(float* d, u32 a0, u32 a1, u32 a2, u32 a3, u32 b0, u32 b1) {
    asm volatile(
        "mma.sync.aligned.m16n8k8.row.col.f32.tf32.tf32.f32 "
        "{%0,%1,%2,%3}, {%4,%5,%6,%7}, {%8,%9}, {%0,%1,%2,%3};"
        : "+f"(d[0]), "+f"(d[1]), "+f"(d[2]), "+f"(d[3])
        : "r"(a0), "r"(a1), "r"(a2), "r"(a3), "r"(b0), "r"(b1));
}

// ---------------------------------------------------------------------------
// tf32 mma.sync GEMM.
//   C[b] (Mr x Nc) = A[b] (Mr x K, K-major) * B
//   BT=false: B[b] is (Nc x K), K-major (NT)
//   BT=true : B[b] is (K x Nc), Nc-major (NN; transpose folded into smem fill)
// SPLIT=3: 3xTF32 (fp32-accurate) ; SPLIT=1: single-pass tf32.
// CTA tile 128x128, kchunk=8, double-buffered fragment-layout smem.
// 8 warps, warp tile 32x64 (2 m-atoms x 8 n-atoms of m16n8k8).
// ---------------------------------------------------------------------------
template<int SPLIT, bool BT>
__global__ void __launch_bounds__(256) mma_gemm(
    const float* __restrict__ A, const float* __restrict__ Bg,
    float* __restrict__ C, int Mr, int Nc, int K)
{
    constexpr int NB = (SPLIT == 3) ? 2 : 1;
    // [stage][buf][row/col 0..127][pair 0..3 (+1 pad)] ; pair j = {elem k=j, k=j+4}
    __shared__ u64 As[2][NB][128][5];
    __shared__ u64 Bs[2][NB][128][5];

    const int t    = threadIdx.x;
    const int lane = t & 31;
    const int wid  = t >> 5;
    const int bz = blockIdx.z;
    const int m0 = blockIdx.y * 128;
    const int n0 = blockIdx.x * 128;
    const float* Ab = A + (size_t)bz * Mr * K;
    const float* Bb = Bg + (size_t)bz * ((size_t)Nc * K);   // same byte count either layout
    float*       Cb = C + (size_t)bz * Mr * Nc;

    float d[2][8][4];
#pragma unroll
    for (int i = 0; i < 2; i++)
#pragma unroll
        for (int na = 0; na < 8; na++)
#pragma unroll
            for (int q = 0; q < 4; q++) d[i][na][q] = 0.0f;

    const int r   = t & 127;
    const bool isA = (t < 128);

    auto fill = [&](int st, int kt) {
        if (isA) {
            const float* s = Ab + (size_t)(m0 + r) * K + kt;
            float x[8];
            *(float4*)&x[0] = *(const float4*)s;
            *(float4*)&x[4] = *(const float4*)(s + 4);
#pragma unroll
            for (int j = 0; j < 4; j++) {
                float h0 = tf32r(x[j]), h1 = tf32r(x[j + 4]);
                As[st][0][r][j] = pk(h0, h1);
                if (SPLIT == 3)
                    As[st][1][r][j] = pk(tf32r(x[j] - h0), tf32r(x[j + 4] - h1));
            }
        } else if (!BT) {
            const float* s = Bb + (size_t)(n0 + r) * K + kt;
            float x[8];
            *(float4*)&x[0] = *(const float4*)s;
            *(float4*)&x[4] = *(const float4*)(s + 4);
#pragma unroll
            for (int j = 0; j < 4; j++) {
                float h0 = tf32r(x[j]), h1 = tf32r(x[j + 4]);
                Bs[st][0][r][j] = pk(h0, h1);
                if (SPLIT == 3)
                    Bs[st][1][r][j] = pk(tf32r(x[j] - h0), tf32r(x[j + 4] - h1));
            }
        } else {
            const int kp = r >> 5, nq = r & 31;          // pair index, n-group
            const float* s0 = Bb + (size_t)(kt + kp) * Nc + n0 + nq * 4;
            const float* s1 = s0 + (size_t)4 * Nc;
            float f0[4], f1[4];
            *(float4*)f0 = *(const float4*)s0;
            *(float4*)f1 = *(const float4*)s1;
#pragma unroll
            for (int j = 0; j < 4; j++) {
                float h0 = tf32r(f0[j]), h1 = tf32r(f1[j]);
                Bs[st][0][nq * 4 + j][kp] = pk(h0, h1);
                if (SPLIT == 3)
                    Bs[st][1][nq * 4 + j][kp] = pk(tf32r(f0[j] - h0), tf32r(f1[j] - h1));
            }
        }
    };

    const int wm = wid >> 1, wn = wid & 1;
    const int g = lane >> 2, lr = lane & 3;

    fill(0, 0);
    __syncthreads();

#pragma unroll 1
    for (int kt = 0; kt < K; kt += 8) {
        const int st = (kt >> 3) & 1;
        if (kt + 8 < K) fill(st ^ 1, kt + 8);

        u64 a0[NB][2], a1[NB][2], bf[NB][8];
#pragma unroll
        for (int b = 0; b < NB; b++)
#pragma unroll
            for (int i = 0; i < 2; i++) {
                a0[b][i] = As[st][b][(wm * 2 + i) * 16 + g][lr];
                a1[b][i] = As[st][b][(wm * 2 + i) * 16 + 8 + g][lr];
            }
#pragma unroll
        for (int b = 0; b < NB; b++)
#pragma unroll
            for (int na = 0; na < 8; na++)
                bf[b][na] = Bs[st][b][wn * 64 + na * 8 + g][lr];

#pragma unroll
        for (int i = 0; i < 2; i++)
#pragma unroll
            for (int na = 0; na < 8; na++) {
                mma8(d[i][na],
                     lo32(a0[0][i]), lo32(a1[0][i]), hi32(a0[0][i]), hi32(a1[0][i]),
                     lo32(bf[0][na]), hi32(bf[0][na]));
                if (SPLIT == 3) {
                    // hi(A) * lo(B)
                    mma8(d[i][na],
                         lo32(a0[0][i]), lo32(a1[0][i]), hi32(a0[0][i]), hi32(a1[0][i]),
                         lo32(bf[1][na]), hi32(bf[1][na]));
                    // lo(A) * hi(B)
                    mma8(d[i][na],
                         lo32(a0[1][i]), lo32(a1[1][i]), hi32(a0[1][i]), hi32(a1[1][i]),
                         lo32(bf[0][na]), hi32(bf[0][na]));
                }
            }
        __syncthreads();
    }

    // epilogue: direct float2 stores (c0,c1) / (c2,c3)
#pragma unroll
    for (int i = 0; i < 2; i++)
#pragma unroll
        for (int na = 0; na < 8; na++) {
            const int row = m0 + wm * 32 + i * 16 + g;
            const int col = n0 + wn * 64 + na * 8 + lr * 2;
            *(float2*)(Cb + (size_t)row * Nc + col)       = make_float2(d[i][na][0], d[i][na][1]);
            *(float2*)(Cb + (size_t)(row + 8) * Nc + col) = make_float2(d[i][na][2], d[i][na][3]);
        }
}

// ---------------------------------------------------------------------------
// Row stats: per (b,n), max and 1/sum(exp) over m (1024 elems).
// ---------------------------------------------------------------------------
__global__ __launch_bounds__(256) void row_stats_kernel(
    const float* __restrict__ S, float* __restrict__ rmax, float* __restrict__ rinv)
{
    const int n = blockIdx.x, b = blockIdx.y;
    const float* row = S + ((size_t)b * NN + n) * MM;
    const int t = threadIdx.x;
    float4 v = *(const float4*)(row + t * 4);

    float mx = fmaxf(fmaxf(v.x, v.y), fmaxf(v.z, v.w));
#pragma unroll
    for (int o = 16; o; o >>= 1) mx = fmaxf(mx, __shfl_xor_sync(0xffffffffu, mx, o));

    __shared__ float smx[8];
    const int w = t >> 5, lane = t & 31;
    if (lane == 0) smx[w] = mx;
    __syncthreads();
    float gmx = smx[0];
#pragma unroll
    for (int i = 1; i < 8; i++) gmx = fmaxf(gmx, smx[i]);

    float s = __expf(v.x - gmx) + __expf(v.y - gmx) + __expf(v.z - gmx) + __expf(v.w - gmx);
#pragma unroll
    for (int o = 16; o; o >>= 1) s += __shfl_xor_sync(0xffffffffu, s, o);

    __shared__ float ssm[8];
    if (lane == 0) ssm[w] = s;
    __syncthreads();
    if (t == 0) {
        float tot = ssm[0];
#pragma unroll
        for (int i = 1; i < 8; i++) tot += ssm[i];
        rmax[b * NN + n] = gmx;
        rinv[b * NN + n] = 1.0f / tot;
    }
}

// ---------------------------------------------------------------------------
// Col stats: online softmax over n for 32 columns per block (coalesced).
// ---------------------------------------------------------------------------
__global__ __launch_bounds__(256) void col_stats_kernel(
    const float* __restrict__ S, float* __restrict__ cmax, float* __restrict__ cinv)
{
    const int b = blockIdx.y;
    const int c0 = blockIdx.x * 32;
    const int t = threadIdx.x, w = t >> 5, lane = t & 31;
    const float* Sb = S + (size_t)b * NN * MM;

    float m_run = -3.0e38f, s_run = 0.0f;
    for (int n = w; n < NN; n += 8) {
        float v = Sb[(size_t)n * MM + c0 + lane];
        if (v <= m_run) {
            s_run += __expf(v - m_run);
        } else {
            s_run = s_run * __expf(m_run - v) + 1.0f;
            m_run = v;
        }
    }

    __shared__ float smx[8][32];
    __shared__ float ssm[8][32];
    smx[w][lane] = m_run;
    ssm[w][lane] = s_run;
    __syncthreads();
    if (w == 0) {
        float m = smx[0][lane], s = ssm[0][lane];
#pragma unroll
        for (int i = 1; i < 8; i++) {
            float m2 = smx[i][lane], s2 = ssm[i][lane];
            float nm = fmaxf(m, m2);
            s = s * __expf(m - nm) + s2 * __expf(m2 - nm);
            m = nm;
        }
        cmax[b * MM + c0 + lane] = m;
        cinv[b * MM + c0 + lane] = 1.0f / s;
    }
}

// ---------------------------------------------------------------------------
// Materialize both normalized weight matrices in one pass over S.
// ---------------------------------------------------------------------------
__global__ __launch_bounds__(256) void softmax_weights_kernel(
    const float* __restrict__ S,
    const float* __restrict__ rmax, const float* __restrict__ rinv,
    const float* __restrict__ cmax, const float* __restrict__ cinv,
    float* __restrict__ Ar, float* __restrict__ AcT)
{
    __shared__ float tile[32][33];
    const int b = blockIdx.z;
    const int n0 = blockIdx.y * 32, m0 = blockIdx.x * 32;
    const int tx = threadIdx.x, ty = threadIdx.y;

    const float cm = cmax[b * MM + m0 + tx];
    const float ci = cinv[b * MM + m0 + tx];

#pragma unroll
    for (int r = ty; r < 32; r += 8) {
        const int n = n0 + r;
        const float s  = S[((size_t)b * NN + n) * MM + m0 + tx];
        const float rm = rmax[b * NN + n];
        const float ri = rinv[b * NN + n];
        Ar[((size_t)b * NN + n) * MM + m0 + tx] = __expf(s - rm) * ri;
        tile[r][tx] = __expf(s - cm) * ci;
    }
    __syncthreads();
#pragma unroll
    for (int r = ty; r < 32; r += 8) {
        const int m = m0 + r;
        AcT[((size_t)b * MM + m) * NN + n0 + tx] = tile[tx][r];
    }
}

// ---------------------------------------------------------------------------
extern "C" void kernel_launch(void* const* d_in, const int* in_sizes, int n_in,
                              void* d_out, int out_size)
{
    (void)in_sizes; (void)n_in; (void)out_size;
    const float* P = (const float*)d_in[0];   // premise    [B][N][D]
    const float* H = (const float*)d_in[1];   // hypothesis [B][M][D]

    float* out1 = (float*)d_out;                              // premise_aligned    [B][N][D]
    float* out2 = (float*)d_out + (size_t)BB * NN * DD;       // hypothesis_aligned [B][M][D]

    float *pS, *pAr, *pAc, *prmax, *prinv, *pcmax, *pcinv;
    cudaGetSymbolAddress((void**)&pS,    g_S);
    cudaGetSymbolAddress((void**)&pAr,   g_Ar);
    cudaGetSymbolAddress((void**)&pAc,   g_Ac);
    cudaGetSymbolAddress((void**)&prmax, g_rmax);
    cudaGetSymbolAddress((void**)&prinv, g_rinv);
    cudaGetSymbolAddress((void**)&pcmax, g_cmax);
    cudaGetSymbolAddress((void**)&pcinv, g_cinv);

    // 1) S = P * H^T   (3xTF32, fp32-accurate logits)
    mma_gemm<3, false><<<dim3(MM / 128, NN / 128, BB), 256>>>(P, H, pS, NN, MM, DD);

    // 2) softmax stats
    row_stats_kernel<<<dim3(NN, BB), 256>>>(pS, prmax, prinv);
    col_stats_kernel<<<dim3(MM / 32, BB), 256>>>(pS, pcmax, pcinv);

    // 3) normalized weights
    softmax_weights_kernel<<<dim3(MM / 32, NN / 32, BB), dim3(32, 8)>>>(
        pS, prmax, prinv, pcmax, pcinv, pAr, pAc);

    // 4) premise_aligned = A_row * H     (tf32, transpose folded into B fill)
    mma_gemm<1, true><<<dim3(DD / 128, NN / 128, BB), 256>>>(pAr, H, out1, NN, DD, MM);

    // 5) hypothesis_aligned = A_colT * P (tf32)
    mma_gemm<1, true><<<dim3(DD / 128, MM / 128, BB), 256>>>(pAc, P, out2, MM, DD, NN);
}

// round 5
// speedup vs baseline: 1.9247x; 1.1612x over previous
#include <cuda_runtime.h>
#include <cstdint>

#define BB 64
#define NN 1024
#define MM 1024
#define DD 512

typedef unsigned long long u64;
typedef unsigned int u32;

// ---------------- scratch (device globals: allocation-free) ----------------
__device__ float g_S [(size_t)BB * NN * MM];
__device__ float g_Ar[(size_t)BB * NN * MM];
__device__ float g_Ac[(size_t)BB * MM * NN];
__device__ float g_rmax[BB * NN];
__device__ float g_rinv[BB * NN];
__device__ float g_cmax[BB * MM];
__device__ float g_cinv[BB * MM];

// ---------------- helpers ----------------
__device__ __forceinline__ float tf32r(float x) {
    float r; asm("cvt.rna.tf32.f32 %0, %1;" : "=f"(r) : "f"(x)); return r;
}
__device__ __forceinline__ u64 pk(float lo, float hi) {
    u64 r;
    asm("mov.b64 %0, {%1, %2};" : "=l"(r) : "r"(__float_as_uint(lo)), "r"(__float_as_uint(hi)));
    return r;
}
__device__ __forceinline__ u32 lo32(u64 v) { return (u32)v; }
__device__ __forceinline__ u32 hi32(u64 v) { return (u32)(v >> 32); }

__device__ __forceinline__ void mma8(float* d, u32 a0, u32 a1, u32 a2, u32 a3, u32 b0, u32 b1) {
    asm volatile(
        "mma.sync.aligned.m16n8k8.row.col.f32.tf32.tf32.f32 "
        "{%0,%1,%2,%3}, {%4,%5,%6,%7}, {%8,%9}, {%0,%1,%2,%3};"
        : "+f"(d[0]), "+f"(d[1]), "+f"(d[2]), "+f"(d[3])
        : "r"(a0), "r"(a1), "r"(a2), "r"(a3), "r"(b0), "r"(b1));
}

// ---------------------------------------------------------------------------
// tf32 mma.sync GEMM, k-chunk 16, double-buffered, fragment-pair smem layout.
//   C[b] (Mr x Nc) = A[b] (Mr x K, K-major) * B
//   BT=false: B[b] is (Nc x K), K-major ; BT=true: B[b] is (K x Nc), Nc-major.
// SPLIT=3: 3xTF32 (fp32-accurate), passes separated to break acc chains.
// CTA 128x128, 256 threads (8 warps, warp tile 32x64), 2 CTAs/SM.
// smem row: 8 u64 pairs + 1 pad (72B). pair (s,j) = {k=s*8+j, k=s*8+j+4}.
// ---------------------------------------------------------------------------
#define SMEM_WORDS(NB) (2 * (NB) * 128 * 9)          // u64 words per operand array

template<int SPLIT, bool BT>
__global__ void __launch_bounds__(256, 2) mma_gemm(
    const float* __restrict__ A, const float* __restrict__ Bg,
    float* __restrict__ C, int Mr, int Nc, int K)
{
    constexpr int NB = (SPLIT == 3) ? 2 : 1;
    extern __shared__ u64 dsm[];
    u64* Asm = dsm;                          // [2][NB][128][9]
    u64* Bsm = dsm + SMEM_WORDS(NB);

    const int t    = threadIdx.x;
    const int lane = t & 31;
    const int wid  = t >> 5;
    const int bz = blockIdx.z;
    const int m0 = blockIdx.y * 128;
    const int n0 = blockIdx.x * 128;
    const float* Ab = A + (size_t)bz * Mr * K;
    const float* Bb = Bg + (size_t)bz * ((size_t)Nc * K);
    float*       Cb = C + (size_t)bz * Mr * Nc;

    float d[2][8][4];
#pragma unroll
    for (int i = 0; i < 2; i++)
#pragma unroll
        for (int na = 0; na < 8; na++)
#pragma unroll
            for (int q = 0; q < 4; q++) d[i][na][q] = 0.0f;

    const int r   = t & 127;
    const bool isA = (t < 128);

    auto idxA = [&](int st, int buf, int row, int pr) {
        return ((size_t)((st * NB + buf) * 128 + row)) * 9 + pr;
    };

    auto fill = [&](int st, int kt) {
        if (isA) {
            const float* s = Ab + (size_t)(m0 + r) * K + kt;
            float x[16];
            *(float4*)&x[0]  = *(const float4*)s;
            *(float4*)&x[4]  = *(const float4*)(s + 4);
            *(float4*)&x[8]  = *(const float4*)(s + 8);
            *(float4*)&x[12] = *(const float4*)(s + 12);
#pragma unroll
            for (int s2 = 0; s2 < 2; s2++)
#pragma unroll
                for (int j = 0; j < 4; j++) {
                    float v0 = x[s2 * 8 + j], v1 = x[s2 * 8 + j + 4];
                    float h0 = tf32r(v0), h1 = tf32r(v1);
                    Asm[idxA(st, 0, r, s2 * 4 + j)] = pk(h0, h1);
                    if (SPLIT == 3)
                        Asm[idxA(st, 1, r, s2 * 4 + j)] = pk(tf32r(v0 - h0), tf32r(v1 - h1));
                }
        } else if (!BT) {
            const float* s = Bb + (size_t)(n0 + r) * K + kt;
            float x[16];
            *(float4*)&x[0]  = *(const float4*)s;
            *(float4*)&x[4]  = *(const float4*)(s + 4);
            *(float4*)&x[8]  = *(const float4*)(s + 8);
            *(float4*)&x[12] = *(const float4*)(s + 12);
#pragma unroll
            for (int s2 = 0; s2 < 2; s2++)
#pragma unroll
                for (int j = 0; j < 4; j++) {
                    float v0 = x[s2 * 8 + j], v1 = x[s2 * 8 + j + 4];
                    float h0 = tf32r(v0), h1 = tf32r(v1);
                    Bsm[idxA(st, 0, r, s2 * 4 + j)] = pk(h0, h1);
                    if (SPLIT == 3)
                        Bsm[idxA(st, 1, r, s2 * 4 + j)] = pk(tf32r(v0 - h0), tf32r(v1 - h1));
                }
        } else {
            const int kp = r >> 5, nq = r & 31;      // k sub-row, n quad
            const float* s0 = Bb + (size_t)(kt + kp) * Nc + n0 + nq * 4;
            float f0[4], f1[4], f2[4], f3[4];
            *(float4*)f0 = *(const float4*)s0;
            *(float4*)f1 = *(const float4*)(s0 + (size_t)4  * Nc);
            *(float4*)f2 = *(const float4*)(s0 + (size_t)8  * Nc);
            *(float4*)f3 = *(const float4*)(s0 + (size_t)12 * Nc);
#pragma unroll
            for (int j = 0; j < 4; j++) {
                float h0 = tf32r(f0[j]), h1 = tf32r(f1[j]);
                float h2 = tf32r(f2[j]), h3 = tf32r(f3[j]);
                Bsm[idxA(st, 0, nq * 4 + j, kp)]     = pk(h0, h1);
                Bsm[idxA(st, 0, nq * 4 + j, 4 + kp)] = pk(h2, h3);
                if (SPLIT == 3) {
                    Bsm[idxA(st, 1, nq * 4 + j, kp)]     = pk(tf32r(f0[j] - h0), tf32r(f1[j] - h1));
                    Bsm[idxA(st, 1, nq * 4 + j, 4 + kp)] = pk(tf32r(f2[j] - h2), tf32r(f3[j] - h3));
                }
            }
        }
    };

    const int wm = wid >> 1, wn = wid & 1;
    const int g = lane >> 2, lr = lane & 3;

    fill(0, 0);
    __syncthreads();

#pragma unroll 1
    for (int kt = 0; kt < K; kt += 16) {
        const int st = (kt >> 4) & 1;
        if (kt + 16 < K) fill(st ^ 1, kt + 16);

#pragma unroll
        for (int ks = 0; ks < 2; ks++) {
            const int pr = ks * 4 + lr;
            // --- hi fragments ---
            u64 aH0[2], aH1[2], bH[8];
#pragma unroll
            for (int i = 0; i < 2; i++) {
                aH0[i] = Asm[idxA(st, 0, (wm * 2 + i) * 16 + g,     pr)];
                aH1[i] = Asm[idxA(st, 0, (wm * 2 + i) * 16 + 8 + g, pr)];
            }
#pragma unroll
            for (int na = 0; na < 8; na++)
                bH[na] = Bsm[idxA(st, 0, wn * 64 + na * 8 + g, pr)];

            // pass 1: hi * hi
#pragma unroll
            for (int i = 0; i < 2; i++)
#pragma unroll
                for (int na = 0; na < 8; na++)
                    mma8(d[i][na],
                         lo32(aH0[i]), lo32(aH1[i]), hi32(aH0[i]), hi32(aH1[i]),
                         lo32(bH[na]), hi32(bH[na]));

            if (SPLIT == 3) {
                // pass 2: hi(A) * lo(B)
                u64 bL[8];
#pragma unroll
                for (int na = 0; na < 8; na++)
                    bL[na] = Bsm[idxA(st, 1, wn * 64 + na * 8 + g, pr)];
#pragma unroll
                for (int i = 0; i < 2; i++)
#pragma unroll
                    for (int na = 0; na < 8; na++)
                        mma8(d[i][na],
                             lo32(aH0[i]), lo32(aH1[i]), hi32(aH0[i]), hi32(aH1[i]),
                             lo32(bL[na]), hi32(bL[na]));

                // pass 3: lo(A) * hi(B)
                u64 aL0[2], aL1[2];
#pragma unroll
                for (int i = 0; i < 2; i++) {
                    aL0[i] = Asm[idxA(st, 1, (wm * 2 + i) * 16 + g,     pr)];
                    aL1[i] = Asm[idxA(st, 1, (wm * 2 + i) * 16 + 8 + g, pr)];
                }
#pragma unroll
                for (int i = 0; i < 2; i++)
#pragma unroll
                    for (int na = 0; na < 8; na++)
                        mma8(d[i][na],
                             lo32(aL0[i]), lo32(aL1[i]), hi32(aL0[i]), hi32(aL1[i]),
                             lo32(bH[na]), hi32(bH[na]));
            }
        }
        __syncthreads();
    }

    // epilogue: direct float2 stores
#pragma unroll
    for (int i = 0; i < 2; i++)
#pragma unroll
        for (int na = 0; na < 8; na++) {
            const int row = m0 + wm * 32 + i * 16 + g;
            const int col = n0 + wn * 64 + na * 8 + lr * 2;
            *(float2*)(Cb + (size_t)row * Nc + col)       = make_float2(d[i][na][0], d[i][na][1]);
            *(float2*)(Cb + (size_t)(row + 8) * Nc + col) = make_float2(d[i][na][2], d[i][na][3]);
        }
}

// ---------------------------------------------------------------------------
// Row stats
// ---------------------------------------------------------------------------
__global__ __launch_bounds__(256) void row_stats_kernel(
    const float* __restrict__ S, float* __restrict__ rmax, float* __restrict__ rinv)
{
    const int n = blockIdx.x, b = blockIdx.y;
    const float* row = S + ((size_t)b * NN + n) * MM;
    const int t = threadIdx.x;
    float4 v = *(const float4*)(row + t * 4);

    float mx = fmaxf(fmaxf(v.x, v.y), fmaxf(v.z, v.w));
#pragma unroll
    for (int o = 16; o; o >>= 1) mx = fmaxf(mx, __shfl_xor_sync(0xffffffffu, mx, o));

    __shared__ float smx[8];
    const int w = t >> 5, lane = t & 31;
    if (lane == 0) smx[w] = mx;
    __syncthreads();
    float gmx = smx[0];
#pragma unroll
    for (int i = 1; i < 8; i++) gmx = fmaxf(gmx, smx[i]);

    float s = __expf(v.x - gmx) + __expf(v.y - gmx) + __expf(v.z - gmx) + __expf(v.w - gmx);
#pragma unroll
    for (int o = 16; o; o >>= 1) s += __shfl_xor_sync(0xffffffffu, s, o);

    __shared__ float ssm[8];
    if (lane == 0) ssm[w] = s;
    __syncthreads();
    if (t == 0) {
        float tot = ssm[0];
#pragma unroll
        for (int i = 1; i < 8; i++) tot += ssm[i];
        rmax[b * NN + n] = gmx;
        rinv[b * NN + n] = 1.0f / tot;
    }
}

// ---------------------------------------------------------------------------
// Col stats (online softmax down columns, coalesced)
// ---------------------------------------------------------------------------
__global__ __launch_bounds__(256) void col_stats_kernel(
    const float* __restrict__ S, float* __restrict__ cmax, float* __restrict__ cinv)
{
    const int b = blockIdx.y;
    const int c0 = blockIdx.x * 32;
    const int t = threadIdx.x, w = t >> 5, lane = t & 31;
    const float* Sb = S + (size_t)b * NN * MM;

    float m_run = -3.0e38f, s_run = 0.0f;
    for (int n = w; n < NN; n += 8) {
        float v = Sb[(size_t)n * MM + c0 + lane];
        if (v <= m_run) {
            s_run += __expf(v - m_run);
        } else {
            s_run = s_run * __expf(m_run - v) + 1.0f;
            m_run = v;
        }
    }

    __shared__ float smx[8][32];
    __shared__ float ssm[8][32];
    smx[w][lane] = m_run;
    ssm[w][lane] = s_run;
    __syncthreads();
    if (w == 0) {
        float m = smx[0][lane], s = ssm[0][lane];
#pragma unroll
        for (int i = 1; i < 8; i++) {
            float m2 = smx[i][lane], s2 = ssm[i][lane];
            float nm = fmaxf(m, m2);
            s = s * __expf(m - nm) + s2 * __expf(m2 - nm);
            m = nm;
        }
        cmax[b * MM + c0 + lane] = m;
        cinv[b * MM + c0 + lane] = 1.0f / s;
    }
}

// ---------------------------------------------------------------------------
// Weights: both softmaxes in one pass (AcT transposed via smem)
// ---------------------------------------------------------------------------
__global__ __launch_bounds__(256) void softmax_weights_kernel(
    const float* __restrict__ S,
    const float* __restrict__ rmax, const float* __restrict__ rinv,
    const float* __restrict__ cmax, const float* __restrict__ cinv,
    float* __restrict__ Ar, float* __restrict__ AcT)
{
    __shared__ float tile[32][33];
    const int b = blockIdx.z;
    const int n0 = blockIdx.y * 32, m0 = blockIdx.x * 32;
    const int tx = threadIdx.x, ty = threadIdx.y;

    const float cm = cmax[b * MM + m0 + tx];
    const float ci = cinv[b * MM + m0 + tx];

#pragma unroll
    for (int r = ty; r < 32; r += 8) {
        const int n = n0 + r;
        const float s  = S[((size_t)b * NN + n) * MM + m0 + tx];
        const float rm = rmax[b * NN + n];
        const float ri = rinv[b * NN + n];
        Ar[((size_t)b * NN + n) * MM + m0 + tx] = __expf(s - rm) * ri;
        tile[r][tx] = __expf(s - cm) * ci;
    }
    __syncthreads();
#pragma unroll
    for (int r = ty; r < 32; r += 8) {
        const int m = m0 + r;
        AcT[((size_t)b * MM + m) * NN + n0 + tx] = tile[tx][r];
    }
}

// ---------------------------------------------------------------------------
extern "C" void kernel_launch(void* const* d_in, const int* in_sizes, int n_in,
                              void* d_out, int out_size)
{
    (void)in_sizes; (void)n_in; (void)out_size;
    const float* P = (const float*)d_in[0];
    const float* H = (const float*)d_in[1];

    float* out1 = (float*)d_out;
    float* out2 = (float*)d_out + (size_t)BB * NN * DD;

    float *pS, *pAr, *pAc, *prmax, *prinv, *pcmax, *pcinv;
    cudaGetSymbolAddress((void**)&pS,    g_S);
    cudaGetSymbolAddress((void**)&pAr,   g_Ar);
    cudaGetSymbolAddress((void**)&pAc,   g_Ac);
    cudaGetSymbolAddress((void**)&prmax, g_rmax);
    cudaGetSymbolAddress((void**)&prinv, g_rinv);
    cudaGetSymbolAddress((void**)&pcmax, g_cmax);
    cudaGetSymbolAddress((void**)&pcinv, g_cinv);

    const int smem3 = 2 * SMEM_WORDS(2) * 8;   // 73728 B
    const int smem1 = 2 * SMEM_WORDS(1) * 8;   // 36864 B
    cudaFuncSetAttribute(mma_gemm<3, false>, cudaFuncAttributeMaxDynamicSharedMemorySize, smem3);
    cudaFuncSetAttribute(mma_gemm<1, true>,  cudaFuncAttributeMaxDynamicSharedMemorySize, smem1);

    // 1) S = P * H^T   (3xTF32, fp32-accurate logits)
    mma_gemm<3, false><<<dim3(MM / 128, NN / 128, BB), 256, smem3>>>(P, H, pS, NN, MM, DD);

    // 2) softmax stats
    row_stats_kernel<<<dim3(NN, BB), 256>>>(pS, prmax, prinv);
    col_stats_kernel<<<dim3(MM / 32, BB), 256>>>(pS, pcmax, pcinv);

    // 3) normalized weights
    softmax_weights_kernel<<<dim3(MM / 32, NN / 32, BB), dim3(32, 8)>>>(
        pS, prmax, prinv, pcmax, pcinv, pAr, pAc);

    // 4) premise_aligned = A_row * H     (tf32, transpose folded into fill)
    mma_gemm<1, true><<<dim3(DD / 128, NN / 128, BB), 256, smem1>>>(pAr, H, out1, NN, DD, MM);

    // 5) hypothesis_aligned = A_colT * P (tf32)
    mma_gemm<1, true><<<dim3(DD / 128, MM / 128, BB), 256, smem1>>>(pAc, P, out2, MM, DD, NN);
}